// round 12
// baseline (speedup 1.0000x reference)
#include <cuda_runtime.h>
#include <cstdint>

#define NN 512
#define DD 256
#define MARGIN 0.2f
#define NMAT 136          // triangular 32x32 tiles

// Scratch (device global, no allocation)
__device__ float g_mat[NN * NN];

// ---------------------------------------------------------------------------
// Packed f32x2 helpers (Blackwell). Negation via exact *-1 / fma preserves
// the TwoSum algebra.
// ---------------------------------------------------------------------------
__device__ __forceinline__ uint64_t pk2(float lo, float hi) {
    uint64_t d; asm("mov.b64 %0, {%1,%2};" : "=l"(d) : "f"(lo), "f"(hi)); return d;
}
__device__ __forceinline__ void upk2(uint64_t v, float& lo, float& hi) {
    asm("mov.b64 {%0,%1}, %2;" : "=f"(lo), "=f"(hi) : "l"(v));
}
__device__ __forceinline__ uint64_t mul2(uint64_t a, uint64_t b) {
    uint64_t d; asm("mul.rn.f32x2 %0, %1, %2;" : "=l"(d) : "l"(a), "l"(b)); return d;
}
__device__ __forceinline__ uint64_t add2(uint64_t a, uint64_t b) {
    uint64_t d; asm("add.rn.f32x2 %0, %1, %2;" : "=l"(d) : "l"(a), "l"(b)); return d;
}
__device__ __forceinline__ uint64_t fma2(uint64_t a, uint64_t b, uint64_t c) {
    uint64_t d; asm("fma.rn.f32x2 %0, %1, %2, %3;" : "=l"(d) : "l"(a), "l"(b), "l"(c)); return d;
}
#define NEG1_2 0xBF800000BF800000ULL
__device__ __forceinline__ uint64_t neg2(uint64_t x) { return mul2(x, NEG1_2); }
__device__ __forceinline__ uint64_t sub2(uint64_t a, uint64_t b) { return fma2(b, NEG1_2, a); }

// Compensated accumulate of product a*b into (S, C): Dot2 (Ogita-Rump-Oishi).
__device__ __forceinline__ void dot2_step(uint64_t a, uint64_t b,
                                          uint64_t& S, uint64_t& C) {
    uint64_t p  = mul2(a, b);
    uint64_t e  = fma2(a, b, neg2(p));   // exact product error
    uint64_t t  = add2(S, p);            // TwoSum(S, p)
    uint64_t bp = sub2(t, S);
    uint64_t d1 = sub2(S, sub2(t, bp));
    uint64_t d2 = sub2(p, bp);
    C = add2(C, add2(e, add2(d1, d2)));
    S = t;
}

// Scalar compensated helpers for row norms (identical rounding since R3)
__device__ __forceinline__ void sq_step(float v, float& s, float& c) {
    float p = __fmul_rn(v, v);
    float e = __fmaf_rn(v, v, -p);
    float t = __fadd_rn(s, p);
    float bp = __fsub_rn(t, s);
    float err = __fadd_rn(__fsub_rn(s, __fsub_rn(t, bp)), __fsub_rn(p, bp));
    c = __fadd_rn(c, __fadd_rn(err, e));
    s = t;
}
__device__ __forceinline__ void cs_merge(float& s, float& c, float s2, float c2) {
    float t = __fadd_rn(s, s2);
    float bp = __fsub_rn(t, s);
    float err = __fadd_rn(__fsub_rn(s, __fsub_rn(t, bp)), __fsub_rn(s2, bp));
    c = __fadd_rn(__fadd_rn(c, c2), err);
    s = t;
}

// ---------------------------------------------------------------------------
// mat kernel (verbatim values since R3): row norms + compensated fp32x2 Gram
// -> distance matrix, 32x32 triangular tile per block, writes (m,n) + (n,m).
// Runs on the side stream, concurrent with the output memset.
// ---------------------------------------------------------------------------
__global__ void __launch_bounds__(256) mat_kernel(const float* __restrict__ emb) {
    __shared__ float As[16][33];
    __shared__ float Bs2[16][34];   // paired: [kk][2*tx + (0|1)] = rows tx, tx+16
    __shared__ float s_sq[64];      // [0:32)=A rows, [32:64)=B rows

    int z = blockIdx.x;
    int tid = threadIdx.x;
    int bj = (int)((sqrtf(8.0f * (float)z + 1.0f) - 1.0f) * 0.5f);
    while ((bj + 1) * (bj + 2) / 2 <= z) bj++;
    while (bj * (bj + 1) / 2 > z) bj--;
    int bi = z - bj * (bj + 1) / 2;

    int m0 = bi * 32, n0 = bj * 32;
    int warp = tid >> 5, lane = tid & 31;
    int tx = tid & 15, ty = tid >> 4;

    #pragma unroll
    for (int r = 0; r < 8; r++) {
        int rl = warp * 8 + r;                       // 0..63
        int grow = (rl < 32) ? (m0 + rl) : (n0 + rl - 32);
        const float4* r4 = (const float4*)(emb + grow * DD);
        float4 x = r4[lane];
        float4 y = r4[lane + 32];
        float s = 0.0f, c = 0.0f;
        sq_step(x.x, s, c); sq_step(x.y, s, c); sq_step(x.z, s, c); sq_step(x.w, s, c);
        sq_step(y.x, s, c); sq_step(y.y, s, c); sq_step(y.z, s, c); sq_step(y.w, s, c);
        #pragma unroll
        for (int off = 16; off > 0; off >>= 1) {
            float s2 = __shfl_xor_sync(0xffffffffu, s, off);
            float c2 = __shfl_xor_sync(0xffffffffu, c, off);
            cs_merge(s, c, s2, c2);
        }
        if (lane == 0) s_sq[rl] = __fadd_rn(s, c);
    }
    __syncthreads();

    uint64_t S0 = 0, C0 = 0, S1 = 0, C1 = 0;

    for (int k0 = 0; k0 < DD; k0 += 16) {
        #pragma unroll
        for (int q = 0; q < 2; q++) {
            int idx = tid + q * 256;
            int r = idx >> 4, kk = idx & 15;
            As[kk][r] = emb[(m0 + r) * DD + k0 + kk];
            Bs2[kk][((r & 15) << 1) | (r >> 4)] = emb[(n0 + r) * DD + k0 + kk];
        }
        __syncthreads();
        #pragma unroll
        for (int kk = 0; kk < 16; kk++) {
            uint64_t b2 = *(const uint64_t*)&Bs2[kk][2 * tx];   // rows (tx, tx+16)
            float a0 = As[kk][ty];
            float a1 = As[kk][ty + 16];
            dot2_step(pk2(a0, a0), b2, S0, C0);
            dot2_step(pk2(a1, a1), b2, S1, C1);
        }
        __syncthreads();
    }

    float d00, d01, d10, d11;
    upk2(add2(S0, C0), d00, d01);
    upk2(add2(S1, C1), d10, d11);

    float dots[2][2] = {{d00, d01}, {d10, d11}};
    #pragma unroll
    for (int i = 0; i < 2; i++) {
        int ml = ty + 16 * i;
        int m = m0 + ml;
        float sm = s_sq[ml];
        #pragma unroll
        for (int j = 0; j < 2; j++) {
            int nl = tx + 16 * j;
            int n = n0 + nl;
            // ref order: (sq[a] + sq[n]) - 2*dot, then clamp — no FMA fusion
            float v = fmaxf(__fsub_rn(__fadd_rn(sm, s_sq[32 + nl]),
                                      __fmul_rn(2.0f, dots[i][j])), 0.0f);
            g_mat[m * NN + n] = v;
            g_mat[n * NN + m] = v;
        }
    }
}

// ---------------------------------------------------------------------------
// kernelB (widened): valid rows only, grid (512 anchors x 8 chunks of 64 p).
// Runs AFTER the full-output memset (overwrites valid rows) and after mat.
// ~2 valid rows per block -> no latency-bound tail.
// Expressions identical to R5 kernelB (bit-identical output values).
// ---------------------------------------------------------------------------
__global__ void __launch_bounds__(256) kernelB(const int* __restrict__ lw,
                                               float4* __restrict__ out) {
    __shared__ __align__(16) float s_key[NN];
    __shared__ int s_not64;

    int a = blockIdx.x;
    int p0 = blockIdx.y << 6;            // 64-p chunk
    int tid = threadIdx.x;

    if (tid == 0) s_not64 = 0;
    __syncthreads();
    // Probe words [1,3,...,511]: within 2KB, valid for both label layouts.
    if (lw[2 * tid + 1] != 0) s_not64 = 1;
    __syncthreads();
    bool is64 = (s_not64 == 0);
    int la = is64 ? lw[2 * a] : lw[a];

    const float INF = __int_as_float(0x7f800000);
    #pragma unroll
    for (int rr = 0; rr < 2; rr++) {
        int n = tid + rr * 256;
        int ln = is64 ? lw[2 * n] : lw[n];
        float m = __ldcg(&g_mat[a * NN + n]);
        s_key[n] = (ln == la) ? INF : m;              // diffs gate
    }
    __syncthreads();

    int warp = tid >> 5, lane = tid & 31;
    const float4* k4 = (const float4*)s_key;

    #pragma unroll
    for (int i = 0; i < 8; i++) {
        int p = p0 + warp * 8 + i;
        int lp = is64 ? lw[2 * p] : lw[p];
        if ((lp == la) && (p != a)) {
            float t = __ldcg(&g_mat[a * NN + p]);     // same stored float as always
            float4* orow = out + ((size_t)a * NN + p) * (NN / 4);
            #pragma unroll
            for (int q = 0; q < 4; q++) {
                float4 f = k4[q * 32 + lane];
                float4 r;
                // ref: (mat[a,n] - mat[a,p]) <= MARGIN, fp32, no fusion.
                r.x = (__fsub_rn(f.x, t) <= MARGIN) ? 1.0f : 0.0f;
                r.y = (__fsub_rn(f.y, t) <= MARGIN) ? 1.0f : 0.0f;
                r.z = (__fsub_rn(f.z, t) <= MARGIN) ? 1.0f : 0.0f;
                r.w = (__fsub_rn(f.w, t) <= MARGIN) ? 1.0f : 0.0f;
                __stcs(&orow[q * 32 + lane], r);
            }
        }
    }
}

// ---------------------------------------------------------------------------
// Side stream + events, created once at static init (host-side objects only,
// no device memory).
// ---------------------------------------------------------------------------
namespace {
struct SideStream {
    cudaStream_t s2 = nullptr;
    cudaEvent_t fork = nullptr, matdone = nullptr;
    SideStream() {
        cudaStreamCreateWithFlags(&s2, cudaStreamNonBlocking);
        cudaEventCreateWithFlags(&fork, cudaEventDisableTiming);
        cudaEventCreateWithFlags(&matdone, cudaEventDisableTiming);
    }
};
SideStream g_ss;
}

extern "C" void kernel_launch(void* const* d_in, const int* in_sizes, int n_in,
                              void* d_out, int out_size) {
    const float* emb = (const float*)d_in[0];
    const int* labels = (const int*)d_in[1];
    (void)in_sizes; (void)n_in;

    // fork: side branch (Gram matrix) runs concurrently with the memset
    cudaEventRecord(g_ss.fork, 0);
    cudaStreamWaitEvent(g_ss.s2, g_ss.fork, 0);
    mat_kernel<<<NMAT, 256, 0, g_ss.s2>>>(emb);
    cudaEventRecord(g_ss.matdone, g_ss.s2);

    // main branch: zero the ENTIRE output via a graph memset node (no SM
    // warps competing with the fill), then overwrite the ~15 valid rows per
    // anchor once mat is done.
    cudaMemsetAsync(d_out, 0, (size_t)out_size * sizeof(float), 0);
    cudaStreamWaitEvent((cudaStream_t)0, g_ss.matdone, 0);
    kernelB<<<dim3(NN, 8), 256>>>(labels, (float4*)d_out);
}

// round 13
// speedup vs baseline: 1.1318x; 1.1318x over previous
#include <cuda_runtime.h>
#include <cstdint>

#define NN 512
#define DD 256
#define MARGIN 0.2f
#define NMAT 136          // triangular 32x32 tiles
#define NZERO 4096        // zero-fill blocks (64 rows each)
#define NBLK (NMAT + NZERO)

// Scratch (device global, no allocation)
__device__ float g_mat[NN * NN];

// ---------------------------------------------------------------------------
// Packed f32x2 helpers (Blackwell). Negation via exact *-1 / fma preserves
// the TwoSum algebra.
// ---------------------------------------------------------------------------
__device__ __forceinline__ uint64_t pk2(float lo, float hi) {
    uint64_t d; asm("mov.b64 %0, {%1,%2};" : "=l"(d) : "f"(lo), "f"(hi)); return d;
}
__device__ __forceinline__ void upk2(uint64_t v, float& lo, float& hi) {
    asm("mov.b64 {%0,%1}, %2;" : "=f"(lo), "=f"(hi) : "l"(v));
}
__device__ __forceinline__ uint64_t mul2(uint64_t a, uint64_t b) {
    uint64_t d; asm("mul.rn.f32x2 %0, %1, %2;" : "=l"(d) : "l"(a), "l"(b)); return d;
}
__device__ __forceinline__ uint64_t add2(uint64_t a, uint64_t b) {
    uint64_t d; asm("add.rn.f32x2 %0, %1, %2;" : "=l"(d) : "l"(a), "l"(b)); return d;
}
__device__ __forceinline__ uint64_t fma2(uint64_t a, uint64_t b, uint64_t c) {
    uint64_t d; asm("fma.rn.f32x2 %0, %1, %2, %3;" : "=l"(d) : "l"(a), "l"(b), "l"(c)); return d;
}
#define NEG1_2 0xBF800000BF800000ULL
__device__ __forceinline__ uint64_t neg2(uint64_t x) { return mul2(x, NEG1_2); }
__device__ __forceinline__ uint64_t sub2(uint64_t a, uint64_t b) { return fma2(b, NEG1_2, a); }

// Compensated accumulate of product a*b into (S, C): Dot2 (Ogita-Rump-Oishi).
__device__ __forceinline__ void dot2_step(uint64_t a, uint64_t b,
                                          uint64_t& S, uint64_t& C) {
    uint64_t p  = mul2(a, b);
    uint64_t e  = fma2(a, b, neg2(p));   // exact product error
    uint64_t t  = add2(S, p);            // TwoSum(S, p)
    uint64_t bp = sub2(t, S);
    uint64_t d1 = sub2(S, sub2(t, bp));
    uint64_t d2 = sub2(p, bp);
    C = add2(C, add2(e, add2(d1, d2)));
    S = t;
}

// Scalar compensated helpers for row norms (identical rounding since R3)
__device__ __forceinline__ void sq_step(float v, float& s, float& c) {
    float p = __fmul_rn(v, v);
    float e = __fmaf_rn(v, v, -p);
    float t = __fadd_rn(s, p);
    float bp = __fsub_rn(t, s);
    float err = __fadd_rn(__fsub_rn(s, __fsub_rn(t, bp)), __fsub_rn(p, bp));
    c = __fadd_rn(c, __fadd_rn(err, e));
    s = t;
}
__device__ __forceinline__ void cs_merge(float& s, float& c, float s2, float c2) {
    float t = __fadd_rn(s, s2);
    float bp = __fsub_rn(t, s);
    float err = __fadd_rn(__fsub_rn(s, __fsub_rn(t, bp)), __fsub_rn(s2, bp));
    c = __fadd_rn(__fadd_rn(c, c2), err);
    s = t;
}

// ---------------------------------------------------------------------------
// mat tile (verbatim values since R3): row norms + compensated fp32x2 Gram ->
// distance matrix, 32x32 triangular tile per block, writes (m,n) + (n,m).
// ---------------------------------------------------------------------------
__device__ void mat_tile(const float* __restrict__ emb, int z, int tid) {
    __shared__ float As[16][33];
    __shared__ float Bs2[16][34];   // paired: [kk][2*tx + (0|1)] = rows tx, tx+16
    __shared__ float s_sq[64];      // [0:32)=A rows, [32:64)=B rows

    int bj = (int)((sqrtf(8.0f * (float)z + 1.0f) - 1.0f) * 0.5f);
    while ((bj + 1) * (bj + 2) / 2 <= z) bj++;
    while (bj * (bj + 1) / 2 > z) bj--;
    int bi = z - bj * (bj + 1) / 2;

    int m0 = bi * 32, n0 = bj * 32;
    int warp = tid >> 5, lane = tid & 31;
    int tx = tid & 15, ty = tid >> 4;

    #pragma unroll
    for (int r = 0; r < 8; r++) {
        int rl = warp * 8 + r;                       // 0..63
        int grow = (rl < 32) ? (m0 + rl) : (n0 + rl - 32);
        const float4* r4 = (const float4*)(emb + grow * DD);
        float4 x = r4[lane];
        float4 y = r4[lane + 32];
        float s = 0.0f, c = 0.0f;
        sq_step(x.x, s, c); sq_step(x.y, s, c); sq_step(x.z, s, c); sq_step(x.w, s, c);
        sq_step(y.x, s, c); sq_step(y.y, s, c); sq_step(y.z, s, c); sq_step(y.w, s, c);
        #pragma unroll
        for (int off = 16; off > 0; off >>= 1) {
            float s2 = __shfl_xor_sync(0xffffffffu, s, off);
            float c2 = __shfl_xor_sync(0xffffffffu, c, off);
            cs_merge(s, c, s2, c2);
        }
        if (lane == 0) s_sq[rl] = __fadd_rn(s, c);
    }
    __syncthreads();

    uint64_t S0 = 0, C0 = 0, S1 = 0, C1 = 0;

    for (int k0 = 0; k0 < DD; k0 += 16) {
        #pragma unroll
        for (int q = 0; q < 2; q++) {
            int idx = tid + q * 256;
            int r = idx >> 4, kk = idx & 15;
            As[kk][r] = emb[(m0 + r) * DD + k0 + kk];
            Bs2[kk][((r & 15) << 1) | (r >> 4)] = emb[(n0 + r) * DD + k0 + kk];
        }
        __syncthreads();
        #pragma unroll
        for (int kk = 0; kk < 16; kk++) {
            uint64_t b2 = *(const uint64_t*)&Bs2[kk][2 * tx];   // rows (tx, tx+16)
            float a0 = As[kk][ty];
            float a1 = As[kk][ty + 16];
            dot2_step(pk2(a0, a0), b2, S0, C0);
            dot2_step(pk2(a1, a1), b2, S1, C1);
        }
        __syncthreads();
    }

    float d00, d01, d10, d11;
    upk2(add2(S0, C0), d00, d01);
    upk2(add2(S1, C1), d10, d11);

    float dots[2][2] = {{d00, d01}, {d10, d11}};
    #pragma unroll
    for (int i = 0; i < 2; i++) {
        int ml = ty + 16 * i;
        int m = m0 + ml;
        float sm = s_sq[ml];
        #pragma unroll
        for (int j = 0; j < 2; j++) {
            int nl = tx + 16 * j;
            int n = n0 + nl;
            // ref order: (sq[a] + sq[n]) - 2*dot, then clamp — no FMA fusion
            float v = fmaxf(__fsub_rn(__fadd_rn(sm, s_sq[32 + nl]),
                                      __fmul_rn(2.0f, dots[i][j])), 0.0f);
            g_mat[m * NN + n] = v;
            g_mat[n * NN + m] = v;
        }
    }
}

// ---------------------------------------------------------------------------
// Kernel A (verbatim R5): blocks [0,136) compute the distance matrix;
// blocks [136, 4232) zero-fill the invalid (a,p) output rows. The Gram
// compute (fma pipe) hides under the ~497MB zero-store stream (DRAM pipe).
// ---------------------------------------------------------------------------
__global__ void __launch_bounds__(256) kernelA(const float* __restrict__ emb,
                                               const int* __restrict__ lw,
                                               float4* __restrict__ out) {
    int tid = threadIdx.x;
    if (blockIdx.x < NMAT) {
        mat_tile(emb, blockIdx.x, tid);
        return;
    }

    __shared__ int s_not64;
    int zb = blockIdx.x - NMAT;          // 0..4095
    int a = zb >> 3;                     // 8 blocks per anchor
    int p0 = (zb & 7) << 6;              // 64-row chunk

    if (tid == 0) s_not64 = 0;
    __syncthreads();
    // Probe words [1,3,...,511]: within 2KB, valid for both label layouts.
    if (lw[2 * tid + 1] != 0) s_not64 = 1;
    __syncthreads();
    bool is64 = (s_not64 == 0);
    int la = is64 ? lw[2 * a] : lw[a];

    int warp = tid >> 5, lane = tid & 31;
    float4 zv = make_float4(0.0f, 0.0f, 0.0f, 0.0f);

    #pragma unroll
    for (int i = 0; i < 8; i++) {
        int p = p0 + warp * 8 + i;
        int lp = is64 ? lw[2 * p] : lw[p];
        bool valid = (lp == la) && (p != a);
        if (!valid) {
            float4* orow = out + ((size_t)a * NN + p) * (NN / 4);
            #pragma unroll
            for (int q = 0; q < 4; q++)
                __stcs(&orow[q * 32 + lane], zv);
        }
    }
}

// ---------------------------------------------------------------------------
// Kernel B (compacted): one block per anchor. Builds the gated s_key row and
// simultaneously compacts the valid p's into a shared list (order-irrelevant:
// each p writes a disjoint output row -> deterministic output). Warps then do
// only ~cnt/8 = 2 iterations instead of a 64-iteration scan.
// Values bit-identical to R5's kernelB.
// ---------------------------------------------------------------------------
__global__ void __launch_bounds__(256) kernelB(const int* __restrict__ lw,
                                               float4* __restrict__ out) {
    __shared__ __align__(16) float s_key[NN];
    __shared__ int s_plist[128];
    __shared__ int s_cnt;
    __shared__ int s_not64;

    int a = blockIdx.x;
    int tid = threadIdx.x;

    if (tid == 0) { s_not64 = 0; s_cnt = 0; }
    __syncthreads();
    // Probe words [1,3,...,511]: within 2KB, valid for both label layouts.
    if (lw[2 * tid + 1] != 0) s_not64 = 1;
    __syncthreads();
    bool is64 = (s_not64 == 0);
    int la = is64 ? lw[2 * a] : lw[a];

    const float INF = __int_as_float(0x7f800000);
    #pragma unroll
    for (int rr = 0; rr < 2; rr++) {
        int n = tid + rr * 256;
        int ln = is64 ? lw[2 * n] : lw[n];
        float m = __ldcg(&g_mat[a * NN + n]);
        bool same = (ln == la);
        s_key[n] = same ? INF : m;                    // diffs gate
        if (same && n != a) {                         // sames gate -> compact
            int ix = atomicAdd(&s_cnt, 1);
            s_plist[ix] = n;
        }
    }
    __syncthreads();

    int cnt = s_cnt;
    int warp = tid >> 5, lane = tid & 31;
    const float4* k4 = (const float4*)s_key;

    for (int i = warp; i < cnt; i += 8) {
        int p = s_plist[i];
        float t = __ldcg(&g_mat[a * NN + p]);         // same stored float as always
        float4* orow = out + ((size_t)a * NN + p) * (NN / 4);
        #pragma unroll
        for (int q = 0; q < 4; q++) {
            float4 f = k4[q * 32 + lane];
            float4 r;
            // ref: (mat[a,n] - mat[a,p]) <= MARGIN, fp32, no fusion.
            r.x = (__fsub_rn(f.x, t) <= MARGIN) ? 1.0f : 0.0f;
            r.y = (__fsub_rn(f.y, t) <= MARGIN) ? 1.0f : 0.0f;
            r.z = (__fsub_rn(f.z, t) <= MARGIN) ? 1.0f : 0.0f;
            r.w = (__fsub_rn(f.w, t) <= MARGIN) ? 1.0f : 0.0f;
            __stcs(&orow[q * 32 + lane], r);
        }
    }
}

// ---------------------------------------------------------------------------
extern "C" void kernel_launch(void* const* d_in, const int* in_sizes, int n_in,
                              void* d_out, int out_size) {
    const float* emb = (const float*)d_in[0];
    const int* labels = (const int*)d_in[1];
    (void)in_sizes; (void)n_in; (void)out_size;

    kernelA<<<NBLK, 256>>>(emb, labels, (float4*)d_out);
    kernelB<<<NN, 256>>>(labels, (float4*)d_out);
}